// round 2
// baseline (speedup 1.0000x reference)
#include <cuda_runtime.h>
#include <math.h>

#define T_SEQ 2048
#define BATCH 2
#define EMB   1024
#define NH    16
#define DH    64
#define NTOK  (BATCH * T_SEQ)   // 4096

// Scratch (allocation-free rule: __device__ globals)
__device__ float g_Q[(size_t)NTOK * EMB];  // [B,H,T,Dh]
__device__ float g_K[(size_t)NTOK * EMB];
__device__ float g_V[(size_t)NTOK * EMB];
__device__ float g_O[(size_t)NTOK * EMB];  // [B,T,E] merged attention output

// ---------------------------------------------------------------------------
// Projection GEMM:  Y[m,n] = sum_k X[m,k] * W[n,k]   (NT, both K-major)
// MODE 0/1/2: X = param, Y = g_Q/g_K/g_V in [B,H,T,Dh] layout
// MODE 3:     X = g_O,   Y = param (d_out), flat [NTOK, EMB]
// 128x128x16 tile, 256 threads, 8x8 register tile per thread.
// ---------------------------------------------------------------------------
template <int MODE>
__global__ void __launch_bounds__(256, 2)
proj_kernel(const float* __restrict__ Xp, const float* __restrict__ W,
            float* __restrict__ Yp)
{
    constexpr int BM = 128, BN = 128, BK = 16;
    __shared__ float As[BK][BM + 4];
    __shared__ float Bs[BK][BN + 4];

    const float* X = (MODE == 3) ? (const float*)g_O : Xp;
    float* Y = (MODE == 0) ? g_Q : (MODE == 1) ? g_K : (MODE == 2) ? g_V : Yp;

    const int m0 = blockIdx.y * BM;
    const int n0 = blockIdx.x * BN;
    const int t  = threadIdx.x;      // 0..255
    const int tx = t & 15;
    const int ty = t >> 4;

    float acc[8][8];
#pragma unroll
    for (int i = 0; i < 8; i++)
#pragma unroll
        for (int j = 0; j < 8; j++) acc[i][j] = 0.f;

    for (int k0 = 0; k0 < EMB; k0 += BK) {
        // Load A and B tiles (transposed to k-major in smem)
#pragma unroll
        for (int s = 0; s < 2; s++) {
            int i   = t + s * 256;        // 0..511
            int row = i >> 2;             // 0..127
            int k4  = (i & 3) << 2;       // 0,4,8,12
            float4 fa = *(const float4*)(X + (size_t)(m0 + row) * EMB + k0 + k4);
            As[k4 + 0][row] = fa.x; As[k4 + 1][row] = fa.y;
            As[k4 + 2][row] = fa.z; As[k4 + 3][row] = fa.w;
            float4 fb = *(const float4*)(W + (size_t)(n0 + row) * EMB + k0 + k4);
            Bs[k4 + 0][row] = fb.x; Bs[k4 + 1][row] = fb.y;
            Bs[k4 + 2][row] = fb.z; Bs[k4 + 3][row] = fb.w;
        }
        __syncthreads();

#pragma unroll
        for (int kk = 0; kk < BK; kk++) {
            float a[8], b[8];
            *(float4*)&a[0] = *(const float4*)&As[kk][ty * 8];
            *(float4*)&a[4] = *(const float4*)&As[kk][ty * 8 + 4];
            *(float4*)&b[0] = *(const float4*)&Bs[kk][tx * 8];
            *(float4*)&b[4] = *(const float4*)&Bs[kk][tx * 8 + 4];
#pragma unroll
            for (int i = 0; i < 8; i++)
#pragma unroll
                for (int j = 0; j < 8; j++)
                    acc[i][j] = fmaf(a[i], b[j], acc[i][j]);
        }
        __syncthreads();
    }

    // Epilogue
#pragma unroll
    for (int i = 0; i < 8; i++) {
        const int m = m0 + ty * 8 + i;
#pragma unroll
        for (int j = 0; j < 8; j++) {
            const int n = n0 + tx * 8 + j;
            if (MODE == 3) {
                Y[(size_t)m * EMB + n] = acc[i][j];
            } else {
                const int b = m / T_SEQ, tt = m % T_SEQ;
                const int h = n >> 6, d = n & 63;
                Y[((size_t)(b * NH + h) * T_SEQ + tt) * DH + d] = acc[i][j];
            }
        }
    }
}

// ---------------------------------------------------------------------------
// Flash attention (causal), fp32.
// One block: 64 queries of one (b,h). 256 threads as 16x16; 4x4 micro-tiles.
// Loops key tiles kt = 0..qt (causal skip above diagonal).
// Dynamic smem: Qs[64][68] + Ks[64][68] + Vs[64][68] + Ps[64][68] = 69632 B.
// ---------------------------------------------------------------------------
__global__ void __launch_bounds__(256)
attn_kernel()
{
    constexpr int BM = 64, BN = 64, LD = BM + 4;  // LD=68, float4-aligned rows
    extern __shared__ float smem[];
    float (*Qs)[LD] = (float (*)[LD])(smem);                 // [DH][LD] d-major
    float (*Ks)[LD] = (float (*)[LD])(smem + DH * LD);       // [DH][LD] d-major
    float (*Vs)[LD] = (float (*)[LD])(smem + 2 * DH * LD);   // [BN][LD] k-major (cols=d)
    float (*Ps)[LD] = (float (*)[LD])(smem + 3 * DH * LD);   // [BN][LD] key-major (cols=q)

    const int bh = blockIdx.y;
    const int qt = gridDim.x - 1 - blockIdx.x;   // heavy tiles scheduled first
    const int q0 = qt * BM;
    const int t  = threadIdx.x;
    const int tx = t & 15;
    const int ty = t >> 4;

    const float* Qg = g_Q + (size_t)bh * T_SEQ * DH;
    const float* Kg = g_K + (size_t)bh * T_SEQ * DH;
    const float* Vg = g_V + (size_t)bh * T_SEQ * DH;

    // Load resident Q tile (transposed to d-major)
#pragma unroll
    for (int s = 0; s < 4; s++) {
        int i   = t + s * 256;        // 0..1023
        int row = i >> 4;             // 0..63
        int d4  = (i & 15) << 2;      // 0..60
        float4 f = *(const float4*)(Qg + (size_t)(q0 + row) * DH + d4);
        Qs[d4 + 0][row] = f.x; Qs[d4 + 1][row] = f.y;
        Qs[d4 + 2][row] = f.z; Qs[d4 + 3][row] = f.w;
    }

    float m_i[4], l_i[4], acc[4][4];
#pragma unroll
    for (int i = 0; i < 4; i++) {
        m_i[i] = -1e30f;
        l_i[i] = 0.f;
#pragma unroll
        for (int j = 0; j < 4; j++) acc[i][j] = 0.f;
    }
    const float scale = 0.125f;  // 1/sqrt(64)

    __syncthreads();

    for (int kt = 0; kt <= qt; kt++) {
        const int k0 = kt * BN;
        // Load K tile (d-major) and V tile (k-major)
#pragma unroll
        for (int s = 0; s < 4; s++) {
            int i   = t + s * 256;
            int row = i >> 4;
            int d4  = (i & 15) << 2;
            float4 f = *(const float4*)(Kg + (size_t)(k0 + row) * DH + d4);
            Ks[d4 + 0][row] = f.x; Ks[d4 + 1][row] = f.y;
            Ks[d4 + 2][row] = f.z; Ks[d4 + 3][row] = f.w;
            float4 g = *(const float4*)(Vg + (size_t)(k0 + row) * DH + d4);
            *(float4*)&Vs[row][d4] = g;
        }
        __syncthreads();

        // S = Q * K^T  (per-thread 4x4)
        float S[4][4];
#pragma unroll
        for (int i = 0; i < 4; i++)
#pragma unroll
            for (int j = 0; j < 4; j++) S[i][j] = 0.f;

#pragma unroll 8
        for (int d = 0; d < DH; d++) {
            float4 qa = *(const float4*)&Qs[d][ty * 4];
            float4 kb = *(const float4*)&Ks[d][tx * 4];
            const float a[4] = {qa.x, qa.y, qa.z, qa.w};
            const float b[4] = {kb.x, kb.y, kb.z, kb.w};
#pragma unroll
            for (int i = 0; i < 4; i++)
#pragma unroll
                for (int j = 0; j < 4; j++)
                    S[i][j] = fmaf(a[i], b[j], S[i][j]);
        }

        // Scale + causal mask (diagonal tile only)
#pragma unroll
        for (int i = 0; i < 4; i++) {
            const int qg = q0 + ty * 4 + i;
#pragma unroll
            for (int j = 0; j < 4; j++) {
                const int kg = k0 + tx * 4 + j;
                S[i][j] = (kt == qt && kg > qg) ? -1e30f : S[i][j] * scale;
            }
        }

        // Online softmax (row reductions across tx via 16-lane shuffles)
#pragma unroll
        for (int i = 0; i < 4; i++) {
            float rm = S[i][0];
            rm = fmaxf(rm, S[i][1]); rm = fmaxf(rm, S[i][2]); rm = fmaxf(rm, S[i][3]);
#pragma unroll
            for (int m = 1; m < 16; m <<= 1)
                rm = fmaxf(rm, __shfl_xor_sync(0xffffffffu, rm, m));
            const float mn    = fmaxf(m_i[i], rm);
            const float alpha = __expf(m_i[i] - mn);
            float rs = 0.f;
#pragma unroll
            for (int j = 0; j < 4; j++) {
                S[i][j] = __expf(S[i][j] - mn);
                rs += S[i][j];
            }
#pragma unroll
            for (int m = 1; m < 16; m <<= 1)
                rs += __shfl_xor_sync(0xffffffffu, rs, m);
            l_i[i] = l_i[i] * alpha + rs;
            m_i[i] = mn;
#pragma unroll
            for (int j = 0; j < 4; j++) acc[i][j] *= alpha;
        }

        // Stage P (transposed to key-major) for the PV GEMM
#pragma unroll
        for (int i = 0; i < 4; i++)
#pragma unroll
            for (int j = 0; j < 4; j++)
                Ps[tx * 4 + j][ty * 4 + i] = S[i][j];
        __syncthreads();

        // acc += P * V
#pragma unroll 8
        for (int k = 0; k < BN; k++) {
            float4 pv = *(const float4*)&Ps[k][ty * 4];
            float4 vv = *(const float4*)&Vs[k][tx * 4];
            const float p[4] = {pv.x, pv.y, pv.z, pv.w};
            const float v4[4] = {vv.x, vv.y, vv.z, vv.w};
#pragma unroll
            for (int i = 0; i < 4; i++)
#pragma unroll
                for (int j = 0; j < 4; j++)
                    acc[i][j] = fmaf(p[i], v4[j], acc[i][j]);
        }
        __syncthreads();  // protect Ks/Vs/Ps before next tile's loads
    }

    // Epilogue: normalize, write merged [B,T,E] layout
    const int b = bh / NH, h = bh % NH;
#pragma unroll
    for (int i = 0; i < 4; i++) {
        const float inv = 1.0f / l_i[i];
        const int q = q0 + ty * 4 + i;
        float4 o;
        o.x = acc[i][0] * inv; o.y = acc[i][1] * inv;
        o.z = acc[i][2] * inv; o.w = acc[i][3] * inv;
        *(float4*)&g_O[(size_t)(b * T_SEQ + q) * EMB + h * DH + tx * 4] = o;
    }
}

// ---------------------------------------------------------------------------
extern "C" void kernel_launch(void* const* d_in, const int* in_sizes, int n_in,
                              void* d_out, int out_size)
{
    (void)in_sizes; (void)n_in; (void)out_size;
    const float* q  = (const float*)d_in[0];
    const float* k  = (const float*)d_in[1];
    const float* v  = (const float*)d_in[2];
    const float* Wq = (const float*)d_in[3];
    const float* Wk = (const float*)d_in[4];
    const float* Wv = (const float*)d_in[5];
    const float* Wo = (const float*)d_in[6];
    float* out = (float*)d_out;

    static bool attr_set = false;
    if (!attr_set) {
        cudaFuncSetAttribute(attn_kernel,
                             cudaFuncAttributeMaxDynamicSharedMemorySize,
                             4 * DH * (64 + 4) * (int)sizeof(float));
        attr_set = true;
    }

    const dim3 gproj(EMB / 128, NTOK / 128);       // (8, 32)
    proj_kernel<0><<<gproj, 256>>>(q, Wq, nullptr);
    proj_kernel<1><<<gproj, 256>>>(k, Wk, nullptr);
    proj_kernel<2><<<gproj, 256>>>(v, Wv, nullptr);

    const dim3 gattn(T_SEQ / 64, BATCH * NH);      // (32, 32)
    attn_kernel<<<gattn, 256, 4 * DH * (64 + 4) * (int)sizeof(float)>>>();

    proj_kernel<3><<<gproj, 256>>>(nullptr, Wo, out);
}

// round 6
// speedup vs baseline: 1.5140x; 1.5140x over previous
#include <cuda_runtime.h>
#include <cuda_bf16.h>
#include <cstdint>
#include <math.h>

#define T_SEQ 2048
#define BATCH 2
#define EMB   1024
#define NH    16
#define DH    64
#define NTOK  (BATCH * T_SEQ)
#define KSPLIT 3072

__device__ float g_Q[(size_t)NTOK * EMB];
__device__ float g_K[(size_t)NTOK * EMB];
__device__ float g_V[(size_t)NTOK * EMB];
__device__ float g_O[(size_t)NTOK * EMB];
__device__ __nv_bfloat16 g_A2[(size_t)NTOK * KSPLIT];
__device__ __nv_bfloat16 g_B2[(size_t)EMB  * KSPLIT];

__device__ __forceinline__ uint32_t smem_u32(const void* p) {
    uint32_t a;
    asm("{ .reg .u64 t; cvta.to.shared.u64 t, %1; cvt.u32.u64 %0, t; }" : "=r"(a) : "l"(p));
    return a;
}
#define CP16(dst, src) \
    asm volatile("cp.async.cg.shared.global [%0], [%1], 16;" :: "r"(dst), "l"(src) : "memory")
#define CP_COMMIT() asm volatile("cp.async.commit_group;" ::: "memory")
#define CP_WAIT1()  asm volatile("cp.async.wait_group 1;" ::: "memory")

// ---------------------------------------------------------------------------
// split-bf16 pack. ISB=0 (acts -> g_A2): [hi|lo|hi]. ISB=1 (wgt -> g_B2): [hi|hi|lo].
// SRC_GO=1: read from g_O (device symbol resolved in device code!).
// ---------------------------------------------------------------------------
template <int ISB, int SRC_GO>
__global__ void conv_kernel(const float* __restrict__ Xp)
{
    const float* X = SRC_GO ? (const float*)g_O : Xp;
    __nv_bfloat16* Y = ISB ? g_B2 : g_A2;

    const int idx = blockIdx.x * 256 + threadIdx.x;   // one float4
    const int m = idx >> 8;
    const int c2 = (idx & 255) << 1;                  // uint32 (bf16x2) index
    float4 f = ((const float4*)X)[idx];
    float xs[4] = {f.x, f.y, f.z, f.w};
    uint32_t hi2[2], lo2[2];
#pragma unroll
    for (int p = 0; p < 2; p++) {
        __nv_bfloat16 h0 = __float2bfloat16_rn(xs[p*2+0]);
        __nv_bfloat16 h1 = __float2bfloat16_rn(xs[p*2+1]);
        __nv_bfloat16 l0 = __float2bfloat16_rn(xs[p*2+0] - __bfloat162float(h0));
        __nv_bfloat16 l1 = __float2bfloat16_rn(xs[p*2+1] - __bfloat162float(h1));
        hi2[p] = ((uint32_t)__bfloat16_as_ushort(h1) << 16) | __bfloat16_as_ushort(h0);
        lo2[p] = ((uint32_t)__bfloat16_as_ushort(l1) << 16) | __bfloat16_as_ushort(l0);
    }
    uint32_t* row = (uint32_t*)(Y + (size_t)m * KSPLIT);
    row[c2] = hi2[0]; row[c2+1] = hi2[1];
    if (ISB) {
        row[512+c2]  = hi2[0]; row[512+c2+1]  = hi2[1];
        row[1024+c2] = lo2[0]; row[1024+c2+1] = lo2[1];
    } else {
        row[512+c2]  = lo2[0]; row[512+c2+1]  = lo2[1];
        row[1024+c2] = hi2[0]; row[1024+c2+1] = hi2[1];
    }
}

// ---------------------------------------------------------------------------
// bf16 mma.sync GEMM: D[m,n] = sum_k A2[m,k]*B2[n,k]. M=4096, N=1024, K=3072.
// 128x128x32 tile, 8 warps (2m x 4n), warp = 64x32 via 4x4 m16n8k16 tiles.
// 3-stage cp.async pipeline. Smem rows padded to 80B (conflict-free ldmatrix).
// ---------------------------------------------------------------------------
#define BKC 32
#define NCH (KSPLIT / BKC)          // 96
#define ROWB 80                      // bytes per smem row (32 bf16 + 16B pad)
#define TILEB (128 * ROWB)           // 10240 per operand tile
#define STAGEB (2 * TILEB)           // 20480
#define NSTG 3
#define SMEM_GEMM (NSTG * STAGEB)    // 61440

template <int MODE>
__global__ void __launch_bounds__(256) gemm_kernel(float* __restrict__ Yp)
{
    extern __shared__ char smem[];
    const int t = threadIdx.x;
    const int wid = t >> 5, lane = t & 31;
    const int wm = wid & 1;          // 0..1  (64 rows each)
    const int wn = wid >> 1;         // 0..3  (32 cols each)
    const int m0 = blockIdx.y * 128;
    const int n0 = blockIdx.x * 128;

    const __nv_bfloat16* Ag = g_A2 + (size_t)m0 * KSPLIT;
    const __nv_bfloat16* Bg = g_B2 + (size_t)n0 * KSPLIT;

    float acc[4][4][4];
#pragma unroll
    for (int mi = 0; mi < 4; mi++)
#pragma unroll
        for (int ni = 0; ni < 4; ni++)
#pragma unroll
            for (int d = 0; d < 4; d++) acc[mi][ni][d] = 0.f;

    // per-thread cp.async segments: 1024 16B segs per stage (A 512 + B 512)
    auto load_stage = [&](int ch, int stg) {
        char* base = smem + stg * STAGEB;
        const size_t koff = (size_t)ch * BKC;
#pragma unroll
        for (int q = 0; q < 4; q++) {
            const int s = t + q * 256;          // 0..1023
            const int tile = s >> 9;            // 0=A 1=B
            const int r = (s >> 2) & 127;
            const int ks = s & 3;
            const uint32_t dst = smem_u32(base + tile * TILEB + r * ROWB + ks * 16);
            const __nv_bfloat16* src = (tile ? Bg : Ag) + (size_t)r * KSPLIT + koff + ks * 8;
            CP16(dst, src);
        }
        CP_COMMIT();
    };

    load_stage(0, 0);
    load_stage(1, 1);

    const int lr  = (lane & 7) + ((lane >> 3) & 1) * 8;   // A ldmatrix row sel
    const int lc8 = ((lane >> 4) & 1) * 8;                // A ldmatrix col sel
    const int bnr = (lane & 7) + ((lane >> 4) & 1) * 8;   // B n-row sel
    const int bkc = ((lane >> 3) & 1) * 8;                // B k-col sel

    for (int ch = 0; ch < NCH; ch++) {
        const int stg = ch % NSTG;
        CP_WAIT1();
        __syncthreads();
        if (ch + NSTG - 1 < NCH) load_stage(ch + NSTG - 1, (ch + NSTG - 1) % NSTG);
        else CP_COMMIT();

        const char* As_ = smem + stg * STAGEB;
        const char* Bs_ = As_ + TILEB;

#pragma unroll
        for (int kk = 0; kk < 2; kk++) {       // two k16 steps
            uint32_t af[4][4];
#pragma unroll
            for (int mi = 0; mi < 4; mi++) {
                const int row = wm * 64 + mi * 16 + lr;
                const uint32_t a = smem_u32(As_ + row * ROWB + (kk * 16 + lc8) * 2);
                asm volatile("ldmatrix.sync.aligned.m8n8.x4.shared.b16 {%0,%1,%2,%3}, [%4];"
                             : "=r"(af[mi][0]), "=r"(af[mi][1]), "=r"(af[mi][2]), "=r"(af[mi][3])
                             : "r"(a) : "memory");
            }
            uint32_t bfr[2][4];
#pragma unroll
            for (int nb = 0; nb < 2; nb++) {
                // mats: {n0-7,k0-7},{n0-7,k8-15},{n8-15,k0-7},{n8-15,k8-15}
                const int nrow = wn * 32 + nb * 16 + bnr;
                const int kcol = kk * 16 + bkc;
                const uint32_t a = smem_u32(Bs_ + nrow * ROWB + kcol * 2);
                asm volatile("ldmatrix.sync.aligned.m8n8.x4.shared.b16 {%0,%1,%2,%3}, [%4];"
                             : "=r"(bfr[nb][0]), "=r"(bfr[nb][1]), "=r"(bfr[nb][2]), "=r"(bfr[nb][3])
                             : "r"(a) : "memory");
            }
#pragma unroll
            for (int mi = 0; mi < 4; mi++)
#pragma unroll
                for (int ni = 0; ni < 4; ni++) {
                    const uint32_t b0 = bfr[ni >> 1][(ni & 1) * 2];
                    const uint32_t b1 = bfr[ni >> 1][(ni & 1) * 2 + 1];
                    asm volatile(
                        "mma.sync.aligned.m16n8k16.row.col.f32.bf16.bf16.f32 "
                        "{%0,%1,%2,%3}, {%4,%5,%6,%7}, {%8,%9}, {%0,%1,%2,%3};"
                        : "+f"(acc[mi][ni][0]), "+f"(acc[mi][ni][1]),
                          "+f"(acc[mi][ni][2]), "+f"(acc[mi][ni][3])
                        : "r"(af[mi][0]), "r"(af[mi][1]), "r"(af[mi][2]), "r"(af[mi][3]),
                          "r"(b0), "r"(b1));
                }
        }
    }

    // epilogue: 4 column slabs of 32, staged through smem for coalesced stores
    float* Y = (MODE == 0) ? g_Q : (MODE == 1) ? g_K : (MODE == 2) ? g_V : Yp;
    float* stg_ = (float*)smem;                 // [128][36]
    const int gid = lane >> 2, tid2 = (lane & 3) * 2;
#pragma unroll 1
    for (int cb = 0; cb < 4; cb++) {
        __syncthreads();
        if (wn == cb) {
#pragma unroll
            for (int mi = 0; mi < 4; mi++)
#pragma unroll
                for (int ni = 0; ni < 4; ni++) {
                    const int r = wm * 64 + mi * 16 + gid;
                    const int c = ni * 8 + tid2;
                    stg_[r * 36 + c]            = acc[mi][ni][0];
                    stg_[r * 36 + c + 1]        = acc[mi][ni][1];
                    stg_[(r + 8) * 36 + c]      = acc[mi][ni][2];
                    stg_[(r + 8) * 36 + c + 1]  = acc[mi][ni][3];
                }
        }
        __syncthreads();
        for (int e = t; e < 1024; e += 256) {
            const int r = e >> 3, c4 = (e & 7) * 4;
            float4 val = *(const float4*)&stg_[r * 36 + c4];
            const int n = n0 + cb * 32 + c4;
            const int m = m0 + r;
            if (MODE == 3) {
                *(float4*)(Y + (size_t)m * EMB + n) = val;
            } else {
                const int b = m >> 11, tt = m & 2047;
                const int h = n >> 6, d = n & 63;
                *(float4*)(Y + ((size_t)(b * NH + h) * T_SEQ + tt) * DH + d) = val;
            }
        }
    }
}

// ---------------- flash attention (fp32, unchanged, known 653us) ------------
__global__ void __launch_bounds__(256) attn_kernel()
{
    constexpr int BM = 64, BN = 64, LD = BM + 4;
    extern __shared__ float sm[];
    float (*Qs)[LD] = (float (*)[LD])(sm);
    float (*Ks)[LD] = (float (*)[LD])(sm + DH*LD);
    float (*Vs)[LD] = (float (*)[LD])(sm + 2*DH*LD);
    float (*Ps)[LD] = (float (*)[LD])(sm + 3*DH*LD);

    const int bh = blockIdx.y;
    const int qt = gridDim.x - 1 - blockIdx.x;
    const int q0 = qt * BM;
    const int t = threadIdx.x;
    const int tx = t & 15, ty = t >> 4;

    const float* Qg = g_Q + (size_t)bh * T_SEQ * DH;
    const float* Kg = g_K + (size_t)bh * T_SEQ * DH;
    const float* Vg = g_V + (size_t)bh * T_SEQ * DH;

#pragma unroll
    for (int s = 0; s < 4; s++) {
        int i = t + s*256, row = i >> 4, d4 = (i & 15) << 2;
        float4 f = *(const float4*)(Qg + (size_t)(q0+row)*DH + d4);
        Qs[d4+0][row] = f.x; Qs[d4+1][row] = f.y; Qs[d4+2][row] = f.z; Qs[d4+3][row] = f.w;
    }
    float m_i[4], l_i[4], acc[4][4];
#pragma unroll
    for (int i = 0; i < 4; i++) {
        m_i[i] = -1e30f; l_i[i] = 0.f;
#pragma unroll
        for (int j = 0; j < 4; j++) acc[i][j] = 0.f;
    }
    const float scale = 0.125f;
    __syncthreads();

    for (int kt = 0; kt <= qt; kt++) {
        const int k0 = kt * BN;
#pragma unroll
        for (int s = 0; s < 4; s++) {
            int i = t + s*256, row = i >> 4, d4 = (i & 15) << 2;
            float4 f = *(const float4*)(Kg + (size_t)(k0+row)*DH + d4);
            Ks[d4+0][row] = f.x; Ks[d4+1][row] = f.y; Ks[d4+2][row] = f.z; Ks[d4+3][row] = f.w;
            *(float4*)&Vs[row][d4] = *(const float4*)(Vg + (size_t)(k0+row)*DH + d4);
        }
        __syncthreads();

        float S[4][4];
#pragma unroll
        for (int i = 0; i < 4; i++)
#pragma unroll
            for (int j = 0; j < 4; j++) S[i][j] = 0.f;
#pragma unroll 8
        for (int d = 0; d < DH; d++) {
            float4 qa = *(const float4*)&Qs[d][ty*4];
            float4 kb = *(const float4*)&Ks[d][tx*4];
            const float a[4] = {qa.x, qa.y, qa.z, qa.w};
            const float b[4] = {kb.x, kb.y, kb.z, kb.w};
#pragma unroll
            for (int i = 0; i < 4; i++)
#pragma unroll
                for (int j = 0; j < 4; j++) S[i][j] = fmaf(a[i], b[j], S[i][j]);
        }
#pragma unroll
        for (int i = 0; i < 4; i++) {
            const int qg = q0 + ty*4 + i;
#pragma unroll
            for (int j = 0; j < 4; j++) {
                const int kg = k0 + tx*4 + j;
                S[i][j] = (kt == qt && kg > qg) ? -1e30f : S[i][j] * scale;
            }
        }
#pragma unroll
        for (int i = 0; i < 4; i++) {
            float rm = fmaxf(fmaxf(S[i][0], S[i][1]), fmaxf(S[i][2], S[i][3]));
#pragma unroll
            for (int m = 1; m < 16; m <<= 1)
                rm = fmaxf(rm, __shfl_xor_sync(0xffffffffu, rm, m));
            const float mn = fmaxf(m_i[i], rm);
            const float alpha = __expf(m_i[i] - mn);
            float rs = 0.f;
#pragma unroll
            for (int j = 0; j < 4; j++) { S[i][j] = __expf(S[i][j] - mn); rs += S[i][j]; }
#pragma unroll
            for (int m = 1; m < 16; m <<= 1)
                rs += __shfl_xor_sync(0xffffffffu, rs, m);
            l_i[i] = l_i[i]*alpha + rs; m_i[i] = mn;
#pragma unroll
            for (int j = 0; j < 4; j++) acc[i][j] *= alpha;
        }
#pragma unroll
        for (int i = 0; i < 4; i++)
#pragma unroll
            for (int j = 0; j < 4; j++) Ps[tx*4+j][ty*4+i] = S[i][j];
        __syncthreads();
#pragma unroll 8
        for (int k = 0; k < BN; k++) {
            float4 pv = *(const float4*)&Ps[k][ty*4];
            float4 vv = *(const float4*)&Vs[k][tx*4];
            const float p[4] = {pv.x, pv.y, pv.z, pv.w};
            const float v4[4] = {vv.x, vv.y, vv.z, vv.w};
#pragma unroll
            for (int i = 0; i < 4; i++)
#pragma unroll
                for (int j = 0; j < 4; j++) acc[i][j] = fmaf(p[i], v4[j], acc[i][j]);
        }
        __syncthreads();
    }
    const int b = bh / NH, h = bh % NH;
#pragma unroll
    for (int i = 0; i < 4; i++) {
        const float inv = 1.0f / l_i[i];
        const int q = q0 + ty*4 + i;
        float4 o;
        o.x = acc[i][0]*inv; o.y = acc[i][1]*inv; o.z = acc[i][2]*inv; o.w = acc[i][3]*inv;
        *(float4*)&g_O[(size_t)(b*T_SEQ + q)*EMB + h*DH + tx*4] = o;
    }
}

extern "C" void kernel_launch(void* const* d_in, const int* in_sizes, int n_in,
                              void* d_out, int out_size)
{
    (void)in_sizes; (void)n_in; (void)out_size;
    const float* q  = (const float*)d_in[0];
    const float* k  = (const float*)d_in[1];
    const float* v  = (const float*)d_in[2];
    const float* Wq = (const float*)d_in[3];
    const float* Wk = (const float*)d_in[4];
    const float* Wv = (const float*)d_in[5];
    const float* Wo = (const float*)d_in[6];
    float* out = (float*)d_out;

    static bool attr_set = false;
    if (!attr_set) {
        cudaFuncSetAttribute(attn_kernel, cudaFuncAttributeMaxDynamicSharedMemorySize, 69632);
        cudaFuncSetAttribute(gemm_kernel<0>, cudaFuncAttributeMaxDynamicSharedMemorySize, SMEM_GEMM);
        cudaFuncSetAttribute(gemm_kernel<1>, cudaFuncAttributeMaxDynamicSharedMemorySize, SMEM_GEMM);
        cudaFuncSetAttribute(gemm_kernel<2>, cudaFuncAttributeMaxDynamicSharedMemorySize, SMEM_GEMM);
        cudaFuncSetAttribute(gemm_kernel<3>, cudaFuncAttributeMaxDynamicSharedMemorySize, SMEM_GEMM);
        attr_set = true;
    }

    const dim3 gg(EMB / 128, NTOK / 128);          // (8, 32)
    const int cact = NTOK * EMB / 4 / 256;         // 4096
    const int cwgt = EMB * EMB / 4 / 256;          // 1024

    conv_kernel<0, 0><<<cact, 256>>>(q);
    conv_kernel<1, 0><<<cwgt, 256>>>(Wq);
    gemm_kernel<0><<<gg, 256, SMEM_GEMM>>>(nullptr);

    conv_kernel<0, 0><<<cact, 256>>>(k);
    conv_kernel<1, 0><<<cwgt, 256>>>(Wk);
    gemm_kernel<1><<<gg, 256, SMEM_GEMM>>>(nullptr);

    conv_kernel<0, 0><<<cact, 256>>>(v);
    conv_kernel<1, 0><<<cwgt, 256>>>(Wv);
    gemm_kernel<2><<<gg, 256, SMEM_GEMM>>>(nullptr);

    attn_kernel<<<dim3(T_SEQ / 64, BATCH * NH), 256, 69632>>>();

    conv_kernel<0, 1><<<cact, 256>>>(nullptr);
    conv_kernel<1, 0><<<cwgt, 256>>>(Wo);
    gemm_kernel<3><<<gg, 256, SMEM_GEMM>>>(out);
}

// round 8
// speedup vs baseline: 2.5751x; 1.7009x over previous
#include <cuda_runtime.h>
#include <cuda_bf16.h>
#include <cstdint>
#include <math.h>

#define T_SEQ 2048
#define BATCH 2
#define EMB   1024
#define NH    16
#define DH    64
#define NTOK  (BATCH * T_SEQ)
#define KSPLIT 3072

__device__ float g_Q[(size_t)NTOK * EMB];
__device__ float g_K[(size_t)NTOK * EMB];
__device__ float g_V[(size_t)NTOK * EMB];
__device__ float g_O[(size_t)NTOK * EMB];
__device__ __nv_bfloat16 g_A2[(size_t)NTOK * KSPLIT];
__device__ __nv_bfloat16 g_B2[(size_t)EMB  * KSPLIT];

__device__ __forceinline__ uint32_t smem_u32(const void* p) {
    uint32_t a;
    asm("{ .reg .u64 t; cvta.to.shared.u64 t, %1; cvt.u32.u64 %0, t; }" : "=r"(a) : "l"(p));
    return a;
}
#define CP16(dst, src) \
    asm volatile("cp.async.cg.shared.global [%0], [%1], 16;" :: "r"(dst), "l"(src) : "memory")
#define CP_COMMIT() asm volatile("cp.async.commit_group;" ::: "memory")
#define CP_WAIT1()  asm volatile("cp.async.wait_group 1;" ::: "memory")

__device__ __forceinline__ uint32_t f2tf32(float x) {
    uint32_t u;
    asm("cvt.rna.tf32.f32 %0, %1;" : "=r"(u) : "f"(x));
    return u;
}
#define MMA_TF32(c, a0, a1, a2, a3, b0, b1)                                 \
    asm volatile("mma.sync.aligned.m16n8k8.row.col.f32.tf32.tf32.f32 "     \
        "{%0,%1,%2,%3}, {%4,%5,%6,%7}, {%8,%9}, {%0,%1,%2,%3};"            \
        : "+f"((c)[0]), "+f"((c)[1]), "+f"((c)[2]), "+f"((c)[3])           \
        : "r"(a0), "r"(a1), "r"(a2), "r"(a3), "r"(b0), "r"(b1))

// ---------------------------------------------------------------------------
// split-bf16 pack. ISB=0 (acts -> g_A2): [hi|lo|hi]. ISB=1 (wgt -> g_B2): [hi|hi|lo].
// ---------------------------------------------------------------------------
template <int ISB, int SRC_GO>
__global__ void conv_kernel(const float* __restrict__ Xp)
{
    const float* X = SRC_GO ? (const float*)g_O : Xp;
    __nv_bfloat16* Y = ISB ? g_B2 : g_A2;

    const int idx = blockIdx.x * 256 + threadIdx.x;
    const int m = idx >> 8;
    const int c2 = (idx & 255) << 1;
    float4 f = ((const float4*)X)[idx];
    float xs[4] = {f.x, f.y, f.z, f.w};
    uint32_t hi2[2], lo2[2];
#pragma unroll
    for (int p = 0; p < 2; p++) {
        __nv_bfloat16 h0 = __float2bfloat16_rn(xs[p*2+0]);
        __nv_bfloat16 h1 = __float2bfloat16_rn(xs[p*2+1]);
        __nv_bfloat16 l0 = __float2bfloat16_rn(xs[p*2+0] - __bfloat162float(h0));
        __nv_bfloat16 l1 = __float2bfloat16_rn(xs[p*2+1] - __bfloat162float(h1));
        hi2[p] = ((uint32_t)__bfloat16_as_ushort(h1) << 16) | __bfloat16_as_ushort(h0);
        lo2[p] = ((uint32_t)__bfloat16_as_ushort(l1) << 16) | __bfloat16_as_ushort(l0);
    }
    uint32_t* row = (uint32_t*)(Y + (size_t)m * KSPLIT);
    row[c2] = hi2[0]; row[c2+1] = hi2[1];
    if (ISB) {
        row[512+c2]  = hi2[0]; row[512+c2+1]  = hi2[1];
        row[1024+c2] = lo2[0]; row[1024+c2+1] = lo2[1];
    } else {
        row[512+c2]  = lo2[0]; row[512+c2+1]  = lo2[1];
        row[1024+c2] = hi2[0]; row[1024+c2+1] = hi2[1];
    }
}

// ---------------------------------------------------------------------------
// bf16 mma.sync GEMM (unchanged, passing): 128x128x32, 3-stage cp.async.
// ---------------------------------------------------------------------------
#define BKC 32
#define NCH (KSPLIT / BKC)
#define ROWB 80
#define TILEB (128 * ROWB)
#define STAGEB (2 * TILEB)
#define NSTG 3
#define SMEM_GEMM (NSTG * STAGEB)

template <int MODE>
__global__ void __launch_bounds__(256) gemm_kernel(float* __restrict__ Yp)
{
    extern __shared__ char smem[];
    const int t = threadIdx.x;
    const int wid = t >> 5, lane = t & 31;
    const int wm = wid & 1;
    const int wn = wid >> 1;
    const int m0 = blockIdx.y * 128;
    const int n0 = blockIdx.x * 128;

    const __nv_bfloat16* Ag = g_A2 + (size_t)m0 * KSPLIT;
    const __nv_bfloat16* Bg = g_B2 + (size_t)n0 * KSPLIT;

    float acc[4][4][4];
#pragma unroll
    for (int mi = 0; mi < 4; mi++)
#pragma unroll
        for (int ni = 0; ni < 4; ni++)
#pragma unroll
            for (int d = 0; d < 4; d++) acc[mi][ni][d] = 0.f;

    auto load_stage = [&](int ch, int stg) {
        char* base = smem + stg * STAGEB;
        const size_t koff = (size_t)ch * BKC;
#pragma unroll
        for (int q = 0; q < 4; q++) {
            const int s = t + q * 256;
            const int tile = s >> 9;
            const int r = (s >> 2) & 127;
            const int ks = s & 3;
            const uint32_t dst = smem_u32(base + tile * TILEB + r * ROWB + ks * 16);
            const __nv_bfloat16* src = (tile ? Bg : Ag) + (size_t)r * KSPLIT + koff + ks * 8;
            CP16(dst, src);
        }
        CP_COMMIT();
    };

    load_stage(0, 0);
    load_stage(1, 1);

    const int lr  = (lane & 7) + ((lane >> 3) & 1) * 8;
    const int lc8 = ((lane >> 4) & 1) * 8;
    const int bnr = (lane & 7) + ((lane >> 4) & 1) * 8;
    const int bkc = ((lane >> 3) & 1) * 8;

    for (int ch = 0; ch < NCH; ch++) {
        const int stg = ch % NSTG;
        CP_WAIT1();
        __syncthreads();
        if (ch + NSTG - 1 < NCH) load_stage(ch + NSTG - 1, (ch + NSTG - 1) % NSTG);
        else CP_COMMIT();

        const char* As_ = smem + stg * STAGEB;
        const char* Bs_ = As_ + TILEB;

#pragma unroll
        for (int kk = 0; kk < 2; kk++) {
            uint32_t af[4][4];
#pragma unroll
            for (int mi = 0; mi < 4; mi++) {
                const int row = wm * 64 + mi * 16 + lr;
                const uint32_t a = smem_u32(As_ + row * ROWB + (kk * 16 + lc8) * 2);
                asm volatile("ldmatrix.sync.aligned.m8n8.x4.shared.b16 {%0,%1,%2,%3}, [%4];"
                             : "=r"(af[mi][0]), "=r"(af[mi][1]), "=r"(af[mi][2]), "=r"(af[mi][3])
                             : "r"(a) : "memory");
            }
            uint32_t bfr[2][4];
#pragma unroll
            for (int nb = 0; nb < 2; nb++) {
                const int nrow = wn * 32 + nb * 16 + bnr;
                const int kcol = kk * 16 + bkc;
                const uint32_t a = smem_u32(Bs_ + nrow * ROWB + kcol * 2);
                asm volatile("ldmatrix.sync.aligned.m8n8.x4.shared.b16 {%0,%1,%2,%3}, [%4];"
                             : "=r"(bfr[nb][0]), "=r"(bfr[nb][1]), "=r"(bfr[nb][2]), "=r"(bfr[nb][3])
                             : "r"(a) : "memory");
            }
#pragma unroll
            for (int mi = 0; mi < 4; mi++)
#pragma unroll
                for (int ni = 0; ni < 4; ni++) {
                    const uint32_t b0 = bfr[ni >> 1][(ni & 1) * 2];
                    const uint32_t b1 = bfr[ni >> 1][(ni & 1) * 2 + 1];
                    asm volatile(
                        "mma.sync.aligned.m16n8k16.row.col.f32.bf16.bf16.f32 "
                        "{%0,%1,%2,%3}, {%4,%5,%6,%7}, {%8,%9}, {%0,%1,%2,%3};"
                        : "+f"(acc[mi][ni][0]), "+f"(acc[mi][ni][1]),
                          "+f"(acc[mi][ni][2]), "+f"(acc[mi][ni][3])
                        : "r"(af[mi][0]), "r"(af[mi][1]), "r"(af[mi][2]), "r"(af[mi][3]),
                          "r"(b0), "r"(b1));
                }
        }
    }

    float* Y = (MODE == 0) ? g_Q : (MODE == 1) ? g_K : (MODE == 2) ? g_V : Yp;
    float* stg_ = (float*)smem;
    const int gid = lane >> 2, tid2 = (lane & 3) * 2;
#pragma unroll 1
    for (int cb = 0; cb < 4; cb++) {
        __syncthreads();
        if (wn == cb) {
#pragma unroll
            for (int mi = 0; mi < 4; mi++)
#pragma unroll
                for (int ni = 0; ni < 4; ni++) {
                    const int r = wm * 64 + mi * 16 + gid;
                    const int c = ni * 8 + tid2;
                    stg_[r * 36 + c]            = acc[mi][ni][0];
                    stg_[r * 36 + c + 1]        = acc[mi][ni][1];
                    stg_[(r + 8) * 36 + c]      = acc[mi][ni][2];
                    stg_[(r + 8) * 36 + c + 1]  = acc[mi][ni][3];
                }
        }
        __syncthreads();
        for (int e = t; e < 1024; e += 256) {
            const int r = e >> 3, c4 = (e & 7) * 4;
            float4 val = *(const float4*)&stg_[r * 36 + c4];
            const int n = n0 + cb * 32 + c4;
            const int m = m0 + r;
            if (MODE == 3) {
                *(float4*)(Y + (size_t)m * EMB + n) = val;
            } else {
                const int b = m >> 11, tt = m & 2047;
                const int h = n >> 6, d = n & 63;
                *(float4*)(Y + ((size_t)(b * NH + h) * T_SEQ + tt) * DH + d) = val;
            }
        }
    }
}

// ---------------------------------------------------------------------------
// tf32 tensor-core flash attention (causal) — explicit fragment addressing.
// Block: 128 queries of one (b,h); 8 warps x 16 query rows. 64-key tiles.
// HW layouts (m16n8k8): A a0=(g,tig) a1=(g+8,tig) a2=(g,tig+4) a3=(g+8,tig+4);
// B b0=(k=tig,n=g) b1=(k=tig+4,n=g); C c01=(g,2tig,2tig+1) c23=(g+8,...).
// P round-trips through a warp-private smem buffer (C-layout store, A-layout load).
// ---------------------------------------------------------------------------
#define KST 68
#define VST 72
#define PST 68
#define SMEM_ATTN ((64 * KST + 64 * VST + 8 * 16 * PST) * 4)   // 70656 B

__global__ void __launch_bounds__(256, 2) attn_tc_kernel()
{
    extern __shared__ float sm[];
    float* Ks = sm;                          // [64][KST]
    float* Vs = sm + 64 * KST;               // [64][VST]
    float* Pw_base = sm + 64 * KST + 64 * VST;  // 8 x [16][PST]

    const int bh = blockIdx.y;
    const int qt = (int)gridDim.x - 1 - (int)blockIdx.x;   // heavy first
    const int q0 = qt * 128;
    const int t = threadIdx.x;
    const int w = t >> 5, lane = t & 31;
    const int g = lane >> 2, tig = lane & 3;

    const float* Qg = g_Q + (size_t)bh * T_SEQ * DH;
    const float* Kg = g_K + (size_t)bh * T_SEQ * DH;
    const float* Vg = g_V + (size_t)bh * T_SEQ * DH;

    // ---- stage Q (x0.125, tf32) at sm[0..128*KST) (overlays Ks/Vs) ----
#pragma unroll
    for (int qq = 0; qq < 8; qq++) {
        const int idx = t + qq * 256;
        const int row = idx >> 4, c4 = (idx & 15) << 2;
        float4 f = *(const float4*)(Qg + (size_t)(q0 + row) * DH + c4);
        uint4 u;
        u.x = f2tf32(f.x * 0.125f); u.y = f2tf32(f.y * 0.125f);
        u.z = f2tf32(f.z * 0.125f); u.w = f2tf32(f.w * 0.125f);
        *(uint4*)(sm + row * KST + c4) = u;
    }
    __syncthreads();

    // ---- persistent Q A-fragments: a0=(g,tig) a1=(g+8,tig) a2=(g,tig+4) a3=(g+8,tig+4)
    uint32_t qf[8][4];
    {
        const float* Qw = sm + (w * 16) * KST;
#pragma unroll
        for (int kc = 0; kc < 8; kc++) {
            qf[kc][0] = *(const uint32_t*)&Qw[g * KST + kc * 8 + tig];
            qf[kc][1] = *(const uint32_t*)&Qw[(g + 8) * KST + kc * 8 + tig];
            qf[kc][2] = *(const uint32_t*)&Qw[g * KST + kc * 8 + tig + 4];
            qf[kc][3] = *(const uint32_t*)&Qw[(g + 8) * KST + kc * 8 + tig + 4];
        }
    }
    __syncthreads();   // Q reads done before K/V staging overwrites

    float o[8][4];
#pragma unroll
    for (int nt = 0; nt < 8; nt++)
#pragma unroll
        for (int j = 0; j < 4; j++) o[nt][j] = 0.f;
    float m0 = -1e30f, m1 = -1e30f, l0 = 0.f, l1 = 0.f;

    float* Pw = Pw_base + w * 16 * PST;

    const int ktmax = 2 * qt + 1;
    for (int kt = 0; kt <= ktmax; kt++) {
        const int k0 = kt * 64;
        // ---- stage K (tf32, stride 68) and V (tf32, stride 72) ----
#pragma unroll
        for (int qq = 0; qq < 4; qq++) {
            const int idx = t + qq * 256;
            const int row = idx >> 4, c4 = (idx & 15) << 2;
            float4 fk = *(const float4*)(Kg + (size_t)(k0 + row) * DH + c4);
            float4 fv = *(const float4*)(Vg + (size_t)(k0 + row) * DH + c4);
            uint4 uk, uv;
            uk.x = f2tf32(fk.x); uk.y = f2tf32(fk.y); uk.z = f2tf32(fk.z); uk.w = f2tf32(fk.w);
            uv.x = f2tf32(fv.x); uv.y = f2tf32(fv.y); uv.z = f2tf32(fv.z); uv.w = f2tf32(fv.w);
            *(uint4*)(Ks + row * KST + c4) = uk;
            *(uint4*)(Vs + row * VST + c4) = uv;
        }
        __syncthreads();

        // ---- S = (Q/8) @ K^T : B frag b0=K[key=nt*8+g][d=kc*8+tig], b1=+4 ----
        float s[8][4];
#pragma unroll
        for (int nt = 0; nt < 8; nt++) {
            s[nt][0] = 0.f; s[nt][1] = 0.f; s[nt][2] = 0.f; s[nt][3] = 0.f;
            const float* Kr = Ks + (nt * 8 + g) * KST + tig;
#pragma unroll
            for (int kc = 0; kc < 8; kc++) {
                const uint32_t b0 = *(const uint32_t*)&Kr[kc * 8];
                const uint32_t b1 = *(const uint32_t*)&Kr[kc * 8 + 4];
                MMA_TF32(s[nt], qf[kc][0], qf[kc][1], qf[kc][2], qf[kc][3], b0, b1);
            }
        }

        // ---- causal mask (C cols = 2tig, 2tig+1) ----
        if (kt >= 2 * qt) {
            const int r0 = q0 + w * 16 + g, r1 = r0 + 8;
#pragma unroll
            for (int nt = 0; nt < 8; nt++) {
                const int c0 = k0 + nt * 8 + 2 * tig;
                if (c0     > r0) s[nt][0] = -1e30f;
                if (c0 + 1 > r0) s[nt][1] = -1e30f;
                if (c0     > r1) s[nt][2] = -1e30f;
                if (c0 + 1 > r1) s[nt][3] = -1e30f;
            }
        }

        // ---- online softmax (rows g: regs 0,1; rows g+8: regs 2,3) ----
        float rm0 = -1e30f, rm1 = -1e30f;
#pragma unroll
        for (int nt = 0; nt < 8; nt++) {
            rm0 = fmaxf(rm0, fmaxf(s[nt][0], s[nt][1]));
            rm1 = fmaxf(rm1, fmaxf(s[nt][2], s[nt][3]));
        }
        rm0 = fmaxf(rm0, __shfl_xor_sync(0xffffffffu, rm0, 1));
        rm0 = fmaxf(rm0, __shfl_xor_sync(0xffffffffu, rm0, 2));
        rm1 = fmaxf(rm1, __shfl_xor_sync(0xffffffffu, rm1, 1));
        rm1 = fmaxf(rm1, __shfl_xor_sync(0xffffffffu, rm1, 2));
        const float mn0 = fmaxf(m0, rm0), mn1 = fmaxf(m1, rm1);
        const float a0 = __expf(m0 - mn0), a1 = __expf(m1 - mn1);
        float rs0 = 0.f, rs1 = 0.f;
#pragma unroll
        for (int nt = 0; nt < 8; nt++) {
            s[nt][0] = __expf(s[nt][0] - mn0); rs0 += s[nt][0];
            s[nt][1] = __expf(s[nt][1] - mn0); rs0 += s[nt][1];
            s[nt][2] = __expf(s[nt][2] - mn1); rs1 += s[nt][2];
            s[nt][3] = __expf(s[nt][3] - mn1); rs1 += s[nt][3];
        }
        rs0 += __shfl_xor_sync(0xffffffffu, rs0, 1);
        rs0 += __shfl_xor_sync(0xffffffffu, rs0, 2);
        rs1 += __shfl_xor_sync(0xffffffffu, rs1, 1);
        rs1 += __shfl_xor_sync(0xffffffffu, rs1, 2);
        l0 = l0 * a0 + rs0; m0 = mn0;
        l1 = l1 * a1 + rs1; m1 = mn1;
#pragma unroll
        for (int nt = 0; nt < 8; nt++) {
            o[nt][0] *= a0; o[nt][1] *= a0;
            o[nt][2] *= a1; o[nt][3] *= a1;
        }

        // ---- P: store C-layout, reload A-layout (warp-private) ----
#pragma unroll
        for (int nt = 0; nt < 8; nt++) {
            *(float2*)&Pw[g * PST + nt * 8 + 2 * tig]       = make_float2(s[nt][0], s[nt][1]);
            *(float2*)&Pw[(g + 8) * PST + nt * 8 + 2 * tig] = make_float2(s[nt][2], s[nt][3]);
        }
        __syncwarp();

        // ---- O += P @ V : pa kc-invariant across nt; vb0=V[key=kc*8+tig][d=nt*8+g]
#pragma unroll
        for (int kc = 0; kc < 8; kc++) {
            const uint32_t pa0 = f2tf32(Pw[g * PST + kc * 8 + tig]);
            const uint32_t pa1 = f2tf32(Pw[(g + 8) * PST + kc * 8 + tig]);
            const uint32_t pa2 = f2tf32(Pw[g * PST + kc * 8 + tig + 4]);
            const uint32_t pa3 = f2tf32(Pw[(g + 8) * PST + kc * 8 + tig + 4]);
            const float* Vr0 = Vs + (kc * 8 + tig) * VST + g;
            const float* Vr1 = Vs + (kc * 8 + tig + 4) * VST + g;
#pragma unroll
            for (int nt = 0; nt < 8; nt++) {
                const uint32_t b0 = *(const uint32_t*)&Vr0[nt * 8];
                const uint32_t b1 = *(const uint32_t*)&Vr1[nt * 8];
                MMA_TF32(o[nt], pa0, pa1, pa2, pa3, b0, b1);
            }
        }
        __syncthreads();   // all smem reads done before next tile staging
    }

    // ---- epilogue: normalize, write merged [B,T,E] (C layout cols 2tig,2tig+1)
    const int b = bh >> 4, h = bh & 15;
    const int r0 = q0 + w * 16 + g;
    const float inv0 = 1.0f / l0, inv1 = 1.0f / l1;
#pragma unroll
    for (int nt = 0; nt < 8; nt++) {
        const int col = h * DH + nt * 8 + 2 * tig;
        float2 v0 = {o[nt][0] * inv0, o[nt][1] * inv0};
        float2 v1 = {o[nt][2] * inv1, o[nt][3] * inv1};
        *(float2*)&g_O[(size_t)(b * T_SEQ + r0) * EMB + col] = v0;
        *(float2*)&g_O[(size_t)(b * T_SEQ + r0 + 8) * EMB + col] = v1;
    }
}

extern "C" void kernel_launch(void* const* d_in, const int* in_sizes, int n_in,
                              void* d_out, int out_size)
{
    (void)in_sizes; (void)n_in; (void)out_size;
    const float* q  = (const float*)d_in[0];
    const float* k  = (const float*)d_in[1];
    const float* v  = (const float*)d_in[2];
    const float* Wq = (const float*)d_in[3];
    const float* Wk = (const float*)d_in[4];
    const float* Wv = (const float*)d_in[5];
    const float* Wo = (const float*)d_in[6];
    float* out = (float*)d_out;

    static bool attr_set = false;
    if (!attr_set) {
        cudaFuncSetAttribute(attn_tc_kernel, cudaFuncAttributeMaxDynamicSharedMemorySize, SMEM_ATTN);
        cudaFuncSetAttribute(gemm_kernel<0>, cudaFuncAttributeMaxDynamicSharedMemorySize, SMEM_GEMM);
        cudaFuncSetAttribute(gemm_kernel<1>, cudaFuncAttributeMaxDynamicSharedMemorySize, SMEM_GEMM);
        cudaFuncSetAttribute(gemm_kernel<2>, cudaFuncAttributeMaxDynamicSharedMemorySize, SMEM_GEMM);
        cudaFuncSetAttribute(gemm_kernel<3>, cudaFuncAttributeMaxDynamicSharedMemorySize, SMEM_GEMM);
        attr_set = true;
    }

    const dim3 gg(EMB / 128, NTOK / 128);
    const int cact = NTOK * EMB / 4 / 256;
    const int cwgt = EMB * EMB / 4 / 256;

    conv_kernel<0, 0><<<cact, 256>>>(q);
    conv_kernel<1, 0><<<cwgt, 256>>>(Wq);
    gemm_kernel<0><<<gg, 256, SMEM_GEMM>>>(nullptr);

    conv_kernel<0, 0><<<cact, 256>>>(k);
    conv_kernel<1, 0><<<cwgt, 256>>>(Wk);
    gemm_kernel<1><<<gg, 256, SMEM_GEMM>>>(nullptr);

    conv_kernel<0, 0><<<cact, 256>>>(v);
    conv_kernel<1, 0><<<cwgt, 256>>>(Wv);
    gemm_kernel<2><<<gg, 256, SMEM_GEMM>>>(nullptr);

    attn_tc_kernel<<<dim3(T_SEQ / 128, BATCH * NH), 256, SMEM_ATTN>>>();

    conv_kernel<0, 1><<<cact, 256>>>(nullptr);
    conv_kernel<1, 0><<<cwgt, 256>>>(Wo);
    gemm_kernel<3><<<gg, 256, SMEM_GEMM>>>(out);
}

// round 9
// speedup vs baseline: 3.0117x; 1.1695x over previous
#include <cuda_runtime.h>
#include <cuda_bf16.h>
#include <cstdint>
#include <math.h>

#define T_SEQ 2048
#define BATCH 2
#define EMB   1024
#define NH    16
#define DH    64
#define NTOK  (BATCH * T_SEQ)
#define KSPLIT 3072

__device__ float g_Q[(size_t)NTOK * EMB];
__device__ float g_K[(size_t)NTOK * EMB];
__device__ float g_V[(size_t)NTOK * EMB];
__device__ __nv_bfloat16 g_A2[(size_t)3 * NTOK * KSPLIT];
__device__ __nv_bfloat16 g_B2[(size_t)3 * EMB  * KSPLIT];

__device__ __forceinline__ uint32_t smem_u32(const void* p) {
    uint32_t a;
    asm("{ .reg .u64 t; cvta.to.shared.u64 t, %1; cvt.u32.u64 %0, t; }" : "=r"(a) : "l"(p));
    return a;
}
#define CP16(dst, src) \
    asm volatile("cp.async.cg.shared.global [%0], [%1], 16;" :: "r"(dst), "l"(src) : "memory")
#define CP_COMMIT() asm volatile("cp.async.commit_group;" ::: "memory")
#define CP_WAIT1()  asm volatile("cp.async.wait_group 1;" ::: "memory")

__device__ __forceinline__ uint32_t f2tf32(float x) {
    uint32_t u;
    asm("cvt.rna.tf32.f32 %0, %1;" : "=r"(u) : "f"(x));
    return u;
}
#define MMA_TF32(c, a0, a1, a2, a3, b0, b1)                                 \
    asm volatile("mma.sync.aligned.m16n8k8.row.col.f32.tf32.tf32.f32 "     \
        "{%0,%1,%2,%3}, {%4,%5,%6,%7}, {%8,%9}, {%0,%1,%2,%3};"            \
        : "+f"((c)[0]), "+f"((c)[1]), "+f"((c)[2]), "+f"((c)[3])           \
        : "r"(a0), "r"(a1), "r"(a2), "r"(a3), "r"(b0), "r"(b1))

__device__ __forceinline__ void split2(float x0, float x1, uint32_t& hp, uint32_t& lp) {
    __nv_bfloat16 h0 = __float2bfloat16_rn(x0);
    __nv_bfloat16 h1 = __float2bfloat16_rn(x1);
    __nv_bfloat16 l0 = __float2bfloat16_rn(x0 - __bfloat162float(h0));
    __nv_bfloat16 l1 = __float2bfloat16_rn(x1 - __bfloat162float(h1));
    hp = ((uint32_t)__bfloat16_as_ushort(h1) << 16) | __bfloat16_as_ushort(h0);
    lp = ((uint32_t)__bfloat16_as_ushort(l1) << 16) | __bfloat16_as_ushort(l0);
}

// ---------------------------------------------------------------------------
// acts conv (batched q,k,v): [hi|lo|hi] -> g_A2[z]. grid 12288.
// ---------------------------------------------------------------------------
__global__ void conv_act(const float* __restrict__ q, const float* __restrict__ k,
                         const float* __restrict__ v)
{
    const int z = blockIdx.x >> 12;
    const float* X = (z == 0) ? q : (z == 1) ? k : v;
    __nv_bfloat16* Y = g_A2 + (size_t)z * NTOK * KSPLIT;

    const int idx = (blockIdx.x & 4095) * 256 + threadIdx.x;
    const int m = idx >> 8;
    const int c2 = (idx & 255) << 1;
    float4 f = ((const float4*)X)[idx];
    uint32_t hi2[2], lo2[2];
    split2(f.x, f.y, hi2[0], lo2[0]);
    split2(f.z, f.w, hi2[1], lo2[1]);
    uint32_t* row = (uint32_t*)(Y + (size_t)m * KSPLIT);
    row[c2] = hi2[0];      row[c2+1] = hi2[1];
    row[512+c2]  = lo2[0]; row[512+c2+1]  = lo2[1];
    row[1024+c2] = hi2[0]; row[1024+c2+1] = hi2[1];
}

// weights conv: [hi|hi|lo] -> g_B2[z]. grid 1024.
__global__ void conv_wgt(const float* __restrict__ W, int z)
{
    __nv_bfloat16* Y = g_B2 + (size_t)z * EMB * KSPLIT;
    const int idx = blockIdx.x * 256 + threadIdx.x;
    const int m = idx >> 8;
    const int c2 = (idx & 255) << 1;
    float4 f = ((const float4*)W)[idx];
    uint32_t hi2[2], lo2[2];
    split2(f.x, f.y, hi2[0], lo2[0]);
    split2(f.z, f.w, hi2[1], lo2[1]);
    uint32_t* row = (uint32_t*)(Y + (size_t)m * KSPLIT);
    row[c2] = hi2[0];      row[c2+1] = hi2[1];
    row[512+c2]  = hi2[0]; row[512+c2+1]  = hi2[1];
    row[1024+c2] = lo2[0]; row[1024+c2+1] = lo2[1];
}

// ---------------------------------------------------------------------------
// bf16 mma.sync GEMM: 128x128x64 chunks, 48 chunks, 3-stage cp.async.
// BATCHED=1: z=blockIdx.z selects QKV; head-layout epilogue.
// BATCHED=0: O-projection, flat epilogue to Yp.
// ---------------------------------------------------------------------------
#define BKC 64
#define NCH (KSPLIT / BKC)           // 48
#define ROWB 144                      // 128B data + 16B pad
#define TILEB (128 * ROWB)            // 18432
#define STAGEB (2 * TILEB)            // 36864
#define NSTG 3
#define SMEM_GEMM (NSTG * STAGEB)     // 110592

template <int BATCHED>
__global__ void __launch_bounds__(256, 2) gemm_kernel(float* __restrict__ Yp)
{
    extern __shared__ char smem[];
    const int t = threadIdx.x;
    const int wid = t >> 5, lane = t & 31;
    const int wm = wid & 1;
    const int wn = wid >> 1;
    const int m0 = blockIdx.y * 128;
    const int n0 = blockIdx.x * 128;
    const int z = BATCHED ? blockIdx.z : 0;

    const __nv_bfloat16* Ag = g_A2 + (size_t)z * NTOK * KSPLIT + (size_t)m0 * KSPLIT;
    const __nv_bfloat16* Bg = g_B2 + (size_t)z * EMB  * KSPLIT + (size_t)n0 * KSPLIT;

    float acc[4][4][4];
#pragma unroll
    for (int mi = 0; mi < 4; mi++)
#pragma unroll
        for (int ni = 0; ni < 4; ni++)
#pragma unroll
            for (int d = 0; d < 4; d++) acc[mi][ni][d] = 0.f;

    // 2048 16B segs/stage over 256 threads: 8 per thread
    auto load_stage = [&](int ch, int stg) {
        char* base = smem + stg * STAGEB;
        const size_t koff = (size_t)ch * BKC;
#pragma unroll
        for (int q = 0; q < 8; q++) {
            const int s = t + q * 256;           // 0..2047
            const int tile = s >> 10;            // 0=A 1=B
            const int r = (s >> 3) & 127;
            const int ks = s & 7;
            const uint32_t dst = smem_u32(base + tile * TILEB + r * ROWB + ks * 16);
            const __nv_bfloat16* src = (tile ? Bg : Ag) + (size_t)r * KSPLIT + koff + ks * 8;
            CP16(dst, src);
        }
        CP_COMMIT();
    };

    load_stage(0, 0);
    load_stage(1, 1);

    const int lr  = (lane & 7) + ((lane >> 3) & 1) * 8;
    const int lc8 = ((lane >> 4) & 1) * 8;
    const int bnr = (lane & 7) + ((lane >> 4) & 1) * 8;
    const int bkc = ((lane >> 3) & 1) * 8;

    for (int ch = 0; ch < NCH; ch++) {
        const int stg = ch % NSTG;
        CP_WAIT1();
        __syncthreads();
        if (ch + 2 < NCH) load_stage(ch + 2, (ch + 2) % NSTG);
        else CP_COMMIT();

        const char* As_ = smem + stg * STAGEB;
        const char* Bs_ = As_ + TILEB;

#pragma unroll
        for (int kk = 0; kk < 4; kk++) {       // four k16 steps (BKC=64)
            uint32_t af[4][4];
#pragma unroll
            for (int mi = 0; mi < 4; mi++) {
                const int row = wm * 64 + mi * 16 + lr;
                const uint32_t a = smem_u32(As_ + row * ROWB + (kk * 16 + lc8) * 2);
                asm volatile("ldmatrix.sync.aligned.m8n8.x4.shared.b16 {%0,%1,%2,%3}, [%4];"
                             : "=r"(af[mi][0]), "=r"(af[mi][1]), "=r"(af[mi][2]), "=r"(af[mi][3])
                             : "r"(a) : "memory");
            }
            uint32_t bfr[2][4];
#pragma unroll
            for (int nb = 0; nb < 2; nb++) {
                const int nrow = wn * 32 + nb * 16 + bnr;
                const int kcol = kk * 16 + bkc;
                const uint32_t a = smem_u32(Bs_ + nrow * ROWB + kcol * 2);
                asm volatile("ldmatrix.sync.aligned.m8n8.x4.shared.b16 {%0,%1,%2,%3}, [%4];"
                             : "=r"(bfr[nb][0]), "=r"(bfr[nb][1]), "=r"(bfr[nb][2]), "=r"(bfr[nb][3])
                             : "r"(a) : "memory");
            }
#pragma unroll
            for (int mi = 0; mi < 4; mi++)
#pragma unroll
                for (int ni = 0; ni < 4; ni++) {
                    const uint32_t b0 = bfr[ni >> 1][(ni & 1) * 2];
                    const uint32_t b1 = bfr[ni >> 1][(ni & 1) * 2 + 1];
                    asm volatile(
                        "mma.sync.aligned.m16n8k16.row.col.f32.bf16.bf16.f32 "
                        "{%0,%1,%2,%3}, {%4,%5,%6,%7}, {%8,%9}, {%0,%1,%2,%3};"
                        : "+f"(acc[mi][ni][0]), "+f"(acc[mi][ni][1]),
                          "+f"(acc[mi][ni][2]), "+f"(acc[mi][ni][3])
                        : "r"(af[mi][0]), "r"(af[mi][1]), "r"(af[mi][2]), "r"(af[mi][3]),
                          "r"(b0), "r"(b1));
                }
        }
    }

    // epilogue: 4 column slabs of 32, smem-staged coalesced stores
    float* Y = BATCHED ? ((z == 0) ? g_Q : (z == 1) ? g_K : g_V) : Yp;
    float* stg_ = (float*)smem;
    const int gid = lane >> 2, tid2 = (lane & 3) * 2;
#pragma unroll 1
    for (int cb = 0; cb < 4; cb++) {
        __syncthreads();
        if (wn == cb) {
#pragma unroll
            for (int mi = 0; mi < 4; mi++)
#pragma unroll
                for (int ni = 0; ni < 4; ni++) {
                    const int r = wm * 64 + mi * 16 + gid;
                    const int c = ni * 8 + tid2;
                    stg_[r * 36 + c]            = acc[mi][ni][0];
                    stg_[r * 36 + c + 1]        = acc[mi][ni][1];
                    stg_[(r + 8) * 36 + c]      = acc[mi][ni][2];
                    stg_[(r + 8) * 36 + c + 1]  = acc[mi][ni][3];
                }
        }
        __syncthreads();
        for (int e = t; e < 1024; e += 256) {
            const int r = e >> 3, c4 = (e & 7) * 4;
            float4 val = *(const float4*)&stg_[r * 36 + c4];
            const int n = n0 + cb * 32 + c4;
            const int m = m0 + r;
            if (!BATCHED) {
                *(float4*)(Y + (size_t)m * EMB + n) = val;
            } else {
                const int b = m >> 11, tt = m & 2047;
                const int h = n >> 6, d = n & 63;
                *(float4*)(Y + ((size_t)(b * NH + h) * T_SEQ + tt) * DH + d) = val;
            }
        }
    }
}

// ---------------------------------------------------------------------------
// tf32 tensor-core flash attention (causal), explicit fragment addressing.
// Epilogue writes split-bf16 [hi|lo|hi] directly into g_A2[z=0] for the O-GEMM.
// ---------------------------------------------------------------------------
#define KST 68
#define VST 72
#define PST 68
#define SMEM_ATTN ((64 * KST + 64 * VST + 8 * 16 * PST) * 4)

__global__ void __launch_bounds__(256, 2) attn_tc_kernel()
{
    extern __shared__ float sm[];
    float* Ks = sm;
    float* Vs = sm + 64 * KST;
    float* Pw_base = sm + 64 * KST + 64 * VST;

    const int bh = blockIdx.y;
    const int qt = (int)gridDim.x - 1 - (int)blockIdx.x;
    const int q0 = qt * 128;
    const int t = threadIdx.x;
    const int w = t >> 5, lane = t & 31;
    const int g = lane >> 2, tig = lane & 3;

    const float* Qg = g_Q + (size_t)bh * T_SEQ * DH;
    const float* Kg = g_K + (size_t)bh * T_SEQ * DH;
    const float* Vg = g_V + (size_t)bh * T_SEQ * DH;

#pragma unroll
    for (int qq = 0; qq < 8; qq++) {
        const int idx = t + qq * 256;
        const int row = idx >> 4, c4 = (idx & 15) << 2;
        float4 f = *(const float4*)(Qg + (size_t)(q0 + row) * DH + c4);
        uint4 u;
        u.x = f2tf32(f.x * 0.125f); u.y = f2tf32(f.y * 0.125f);
        u.z = f2tf32(f.z * 0.125f); u.w = f2tf32(f.w * 0.125f);
        *(uint4*)(sm + row * KST + c4) = u;
    }
    __syncthreads();

    uint32_t qf[8][4];
    {
        const float* Qw = sm + (w * 16) * KST;
#pragma unroll
        for (int kc = 0; kc < 8; kc++) {
            qf[kc][0] = *(const uint32_t*)&Qw[g * KST + kc * 8 + tig];
            qf[kc][1] = *(const uint32_t*)&Qw[(g + 8) * KST + kc * 8 + tig];
            qf[kc][2] = *(const uint32_t*)&Qw[g * KST + kc * 8 + tig + 4];
            qf[kc][3] = *(const uint32_t*)&Qw[(g + 8) * KST + kc * 8 + tig + 4];
        }
    }
    __syncthreads();

    float o[8][4];
#pragma unroll
    for (int nt = 0; nt < 8; nt++)
#pragma unroll
        for (int j = 0; j < 4; j++) o[nt][j] = 0.f;
    float m0 = -1e30f, m1 = -1e30f, l0 = 0.f, l1 = 0.f;

    float* Pw = Pw_base + w * 16 * PST;

    const int ktmax = 2 * qt + 1;
    for (int kt = 0; kt <= ktmax; kt++) {
        const int k0 = kt * 64;
#pragma unroll
        for (int qq = 0; qq < 4; qq++) {
            const int idx = t + qq * 256;
            const int row = idx >> 4, c4 = (idx & 15) << 2;
            float4 fk = *(const float4*)(Kg + (size_t)(k0 + row) * DH + c4);
            float4 fv = *(const float4*)(Vg + (size_t)(k0 + row) * DH + c4);
            uint4 uk, uv;
            uk.x = f2tf32(fk.x); uk.y = f2tf32(fk.y); uk.z = f2tf32(fk.z); uk.w = f2tf32(fk.w);
            uv.x = f2tf32(fv.x); uv.y = f2tf32(fv.y); uv.z = f2tf32(fv.z); uv.w = f2tf32(fv.w);
            *(uint4*)(Ks + row * KST + c4) = uk;
            *(uint4*)(Vs + row * VST + c4) = uv;
        }
        __syncthreads();

        float s[8][4];
#pragma unroll
        for (int nt = 0; nt < 8; nt++) {
            s[nt][0] = 0.f; s[nt][1] = 0.f; s[nt][2] = 0.f; s[nt][3] = 0.f;
            const float* Kr = Ks + (nt * 8 + g) * KST + tig;
#pragma unroll
            for (int kc = 0; kc < 8; kc++) {
                const uint32_t b0 = *(const uint32_t*)&Kr[kc * 8];
                const uint32_t b1 = *(const uint32_t*)&Kr[kc * 8 + 4];
                MMA_TF32(s[nt], qf[kc][0], qf[kc][1], qf[kc][2], qf[kc][3], b0, b1);
            }
        }

        if (kt >= 2 * qt) {
            const int r0 = q0 + w * 16 + g, r1 = r0 + 8;
#pragma unroll
            for (int nt = 0; nt < 8; nt++) {
                const int c0 = k0 + nt * 8 + 2 * tig;
                if (c0     > r0) s[nt][0] = -1e30f;
                if (c0 + 1 > r0) s[nt][1] = -1e30f;
                if (c0     > r1) s[nt][2] = -1e30f;
                if (c0 + 1 > r1) s[nt][3] = -1e30f;
            }
        }

        float rm0 = -1e30f, rm1 = -1e30f;
#pragma unroll
        for (int nt = 0; nt < 8; nt++) {
            rm0 = fmaxf(rm0, fmaxf(s[nt][0], s[nt][1]));
            rm1 = fmaxf(rm1, fmaxf(s[nt][2], s[nt][3]));
        }
        rm0 = fmaxf(rm0, __shfl_xor_sync(0xffffffffu, rm0, 1));
        rm0 = fmaxf(rm0, __shfl_xor_sync(0xffffffffu, rm0, 2));
        rm1 = fmaxf(rm1, __shfl_xor_sync(0xffffffffu, rm1, 1));
        rm1 = fmaxf(rm1, __shfl_xor_sync(0xffffffffu, rm1, 2));
        const float mn0 = fmaxf(m0, rm0), mn1 = fmaxf(m1, rm1);
        const float a0 = __expf(m0 - mn0), a1 = __expf(m1 - mn1);
        float rs0 = 0.f, rs1 = 0.f;
#pragma unroll
        for (int nt = 0; nt < 8; nt++) {
            s[nt][0] = __expf(s[nt][0] - mn0); rs0 += s[nt][0];
            s[nt][1] = __expf(s[nt][1] - mn0); rs0 += s[nt][1];
            s[nt][2] = __expf(s[nt][2] - mn1); rs1 += s[nt][2];
            s[nt][3] = __expf(s[nt][3] - mn1); rs1 += s[nt][3];
        }
        rs0 += __shfl_xor_sync(0xffffffffu, rs0, 1);
        rs0 += __shfl_xor_sync(0xffffffffu, rs0, 2);
        rs1 += __shfl_xor_sync(0xffffffffu, rs1, 1);
        rs1 += __shfl_xor_sync(0xffffffffu, rs1, 2);
        l0 = l0 * a0 + rs0; m0 = mn0;
        l1 = l1 * a1 + rs1; m1 = mn1;
#pragma unroll
        for (int nt = 0; nt < 8; nt++) {
            o[nt][0] *= a0; o[nt][1] *= a0;
            o[nt][2] *= a1; o[nt][3] *= a1;
        }

#pragma unroll
        for (int nt = 0; nt < 8; nt++) {
            *(float2*)&Pw[g * PST + nt * 8 + 2 * tig]       = make_float2(s[nt][0], s[nt][1]);
            *(float2*)&Pw[(g + 8) * PST + nt * 8 + 2 * tig] = make_float2(s[nt][2], s[nt][3]);
        }
        __syncwarp();

#pragma unroll
        for (int kc = 0; kc < 8; kc++) {
            const uint32_t pa0 = f2tf32(Pw[g * PST + kc * 8 + tig]);
            const uint32_t pa1 = f2tf32(Pw[(g + 8) * PST + kc * 8 + tig]);
            const uint32_t pa2 = f2tf32(Pw[g * PST + kc * 8 + tig + 4]);
            const uint32_t pa3 = f2tf32(Pw[(g + 8) * PST + kc * 8 + tig + 4]);
            const float* Vr0 = Vs + (kc * 8 + tig) * VST + g;
            const float* Vr1 = Vs + (kc * 8 + tig + 4) * VST + g;
#pragma unroll
            for (int nt = 0; nt < 8; nt++) {
                const uint32_t b0 = *(const uint32_t*)&Vr0[nt * 8];
                const uint32_t b1 = *(const uint32_t*)&Vr1[nt * 8];
                MMA_TF32(o[nt], pa0, pa1, pa2, pa3, b0, b1);
            }
        }
        __syncthreads();
    }

    // epilogue: normalize + split-bf16 [hi|lo|hi] directly into g_A2 (z=0)
    const int b = bh >> 4, h = bh & 15;
    const int r0 = q0 + w * 16 + g;
    const float inv0 = 1.0f / l0, inv1 = 1.0f / l1;
    uint32_t* row0 = (uint32_t*)(g_A2 + (size_t)(b * T_SEQ + r0) * KSPLIT);
    uint32_t* row1 = (uint32_t*)(g_A2 + (size_t)(b * T_SEQ + r0 + 8) * KSPLIT);
#pragma unroll
    for (int nt = 0; nt < 8; nt++) {
        const int c2 = (h * DH + nt * 8 + 2 * tig) >> 1;
        uint32_t hp, lp;
        split2(o[nt][0] * inv0, o[nt][1] * inv0, hp, lp);
        row0[c2] = hp; row0[512 + c2] = lp; row0[1024 + c2] = hp;
        split2(o[nt][2] * inv1, o[nt][3] * inv1, hp, lp);
        row1[c2] = hp; row1[512 + c2] = lp; row1[1024 + c2] = hp;
    }
}

extern "C" void kernel_launch(void* const* d_in, const int* in_sizes, int n_in,
                              void* d_out, int out_size)
{
    (void)in_sizes; (void)n_in; (void)out_size;
    const float* q  = (const float*)d_in[0];
    const float* k  = (const float*)d_in[1];
    const float* v  = (const float*)d_in[2];
    const float* Wq = (const float*)d_in[3];
    const float* Wk = (const float*)d_in[4];
    const float* Wv = (const float*)d_in[5];
    const float* Wo = (const float*)d_in[6];
    float* out = (float*)d_out;

    static bool attr_set = false;
    if (!attr_set) {
        cudaFuncSetAttribute(attn_tc_kernel, cudaFuncAttributeMaxDynamicSharedMemorySize, SMEM_ATTN);
        cudaFuncSetAttribute(gemm_kernel<0>, cudaFuncAttributeMaxDynamicSharedMemorySize, SMEM_GEMM);
        cudaFuncSetAttribute(gemm_kernel<1>, cudaFuncAttributeMaxDynamicSharedMemorySize, SMEM_GEMM);
        attr_set = true;
    }

    conv_act<<<12288, 256>>>(q, k, v);
    conv_wgt<<<1024, 256>>>(Wq, 0);
    conv_wgt<<<1024, 256>>>(Wk, 1);
    conv_wgt<<<1024, 256>>>(Wv, 2);
    gemm_kernel<1><<<dim3(EMB / 128, NTOK / 128, 3), 256, SMEM_GEMM>>>(nullptr);

    attn_tc_kernel<<<dim3(T_SEQ / 128, BATCH * NH), 256, SMEM_ATTN>>>();

    conv_wgt<<<1024, 256>>>(Wo, 0);
    gemm_kernel<0><<<dim3(EMB / 128, NTOK / 128), 256, SMEM_GEMM>>>(out);
}

// round 10
// speedup vs baseline: 3.7138x; 1.2331x over previous
#include <cuda_runtime.h>
#include <cuda_bf16.h>
#include <cstdint>
#include <math.h>

#define T_SEQ 2048
#define BATCH 2
#define EMB   1024
#define NH    16
#define DH    64
#define NTOK  (BATCH * T_SEQ)

__device__ float g_Q[(size_t)NTOK * EMB];
__device__ float g_K[(size_t)NTOK * EMB];
__device__ float g_V[(size_t)NTOK * EMB];
__device__ uint32_t g_A2[(size_t)3 * NTOK * EMB];   // tf32 activations
__device__ uint32_t g_B2[(size_t)3 * EMB  * EMB];   // tf32 weights

__device__ __forceinline__ uint32_t smem_u32(const void* p) {
    uint32_t a;
    asm("{ .reg .u64 t; cvta.to.shared.u64 t, %1; cvt.u32.u64 %0, t; }" : "=r"(a) : "l"(p));
    return a;
}
#define CP16(dst, src) \
    asm volatile("cp.async.cg.shared.global [%0], [%1], 16;" :: "r"(dst), "l"(src) : "memory")
#define CP_COMMIT() asm volatile("cp.async.commit_group;" ::: "memory")
#define CP_WAIT1()  asm volatile("cp.async.wait_group 1;" ::: "memory")

__device__ __forceinline__ uint32_t f2tf32(float x) {
    uint32_t u;
    asm("cvt.rna.tf32.f32 %0, %1;" : "=r"(u) : "f"(x));
    return u;
}
#define MMA_TF32(c, a0, a1, a2, a3, b0, b1)                                 \
    asm volatile("mma.sync.aligned.m16n8k8.row.col.f32.tf32.tf32.f32 "     \
        "{%0,%1,%2,%3}, {%4,%5,%6,%7}, {%8,%9}, {%0,%1,%2,%3};"            \
        : "+f"((c)[0]), "+f"((c)[1]), "+f"((c)[2]), "+f"((c)[3])           \
        : "r"(a0), "r"(a1), "r"(a2), "r"(a3), "r"(b0), "r"(b1))

// ---------------------------------------------------------------------------
// tf32 converts: acts (q,k,v batched) and weights.
// ---------------------------------------------------------------------------
__global__ void conv_act(const float* __restrict__ q, const float* __restrict__ k,
                         const float* __restrict__ v)
{
    const int z = blockIdx.x >> 12;
    const float* X = (z == 0) ? q : (z == 1) ? k : v;
    uint32_t* Y = g_A2 + (size_t)z * NTOK * EMB;
    const int idx = (blockIdx.x & 4095) * 256 + threadIdx.x;
    float4 f = ((const float4*)X)[idx];
    uint4 u;
    u.x = f2tf32(f.x); u.y = f2tf32(f.y); u.z = f2tf32(f.z); u.w = f2tf32(f.w);
    ((uint4*)Y)[idx] = u;
}

__global__ void conv_wgt(const float* __restrict__ W, int z)
{
    uint32_t* Y = g_B2 + (size_t)z * EMB * EMB;
    const int idx = blockIdx.x * 256 + threadIdx.x;
    float4 f = ((const float4*)W)[idx];
    uint4 u;
    u.x = f2tf32(f.x); u.y = f2tf32(f.y); u.z = f2tf32(f.z); u.w = f2tf32(f.w);
    ((uint4*)Y)[idx] = u;
}

// ---------------------------------------------------------------------------
// tf32 mma.sync GEMM: D[m,n] = sum_k A[m,k]*B[n,k]. M=4096, N=1024, K=1024.
// 128x128 tile, BKC=32 tf32 (128B/row), 32 chunks, 3-stage cp.async.
// ldmatrix.x4.b16 aliased onto tf32 words (verified per-mat address mapping).
// ---------------------------------------------------------------------------
#define BKC 32
#define NCH (EMB / BKC)               // 32
#define ROWB 144
#define TILEB (128 * ROWB)
#define STAGEB (2 * TILEB)            // 36864
#define NSTG 3
#define SMEM_GEMM (NSTG * STAGEB)     // 110592

template <int BATCHED>
__global__ void __launch_bounds__(256, 2) gemm_kernel(float* __restrict__ Yp)
{
    extern __shared__ char smem[];
    const int t = threadIdx.x;
    const int wid = t >> 5, lane = t & 31;
    const int wm = wid & 1;
    const int wn = wid >> 1;
    const int m0 = blockIdx.y * 128;
    const int n0 = blockIdx.x * 128;
    const int z = BATCHED ? blockIdx.z : 0;

    const uint32_t* Ag = g_A2 + (size_t)z * NTOK * EMB + (size_t)m0 * EMB;
    const uint32_t* Bg = g_B2 + (size_t)z * EMB  * EMB + (size_t)n0 * EMB;

    float acc[4][4][4];
#pragma unroll
    for (int mi = 0; mi < 4; mi++)
#pragma unroll
        for (int ni = 0; ni < 4; ni++)
#pragma unroll
            for (int d = 0; d < 4; d++) acc[mi][ni][d] = 0.f;

    // 2048 16B segs per stage over 256 threads: 8 per thread
    auto load_stage = [&](int ch, int stg) {
        char* base = smem + stg * STAGEB;
        const size_t koff = (size_t)ch * BKC;
#pragma unroll
        for (int q = 0; q < 8; q++) {
            const int s = t + q * 256;
            const int tile = s >> 10;
            const int r = (s >> 3) & 127;
            const int ks = s & 7;
            const uint32_t dst = smem_u32(base + tile * TILEB + r * ROWB + ks * 16);
            const uint32_t* src = (tile ? Bg : Ag) + (size_t)r * EMB + koff + ks * 4;
            CP16(dst, src);
        }
        CP_COMMIT();
    };

    load_stage(0, 0);
    load_stage(1, 1);

    // A mats: sel=lane>>3: row += (sel&1)*8, col += (sel>>1)*4 (tf32 cols)
    const int ar = (lane & 7) + ((lane >> 3) & 1) * 8;
    const int ac4 = ((lane >> 4) & 1) * 4;
    // B mats: row += (sel>>1)*8, col += (sel&1)*4
    const int br = (lane & 7) + ((lane >> 4) & 1) * 8;
    const int bc4 = ((lane >> 3) & 1) * 4;

    for (int ch = 0; ch < NCH; ch++) {
        const int stg = ch % NSTG;
        CP_WAIT1();
        __syncthreads();
        if (ch + 2 < NCH) load_stage(ch + 2, (ch + 2) % NSTG);
        else CP_COMMIT();

        const char* As_ = smem + stg * STAGEB;
        const char* Bs_ = As_ + TILEB;

#pragma unroll
        for (int kk = 0; kk < 4; kk++) {       // four k8 steps (BKC=32 tf32)
            uint32_t af[4][4];
#pragma unroll
            for (int mi = 0; mi < 4; mi++) {
                const int row = wm * 64 + mi * 16 + ar;
                const uint32_t a = smem_u32(As_ + row * ROWB + (kk * 8 + ac4) * 4);
                asm volatile("ldmatrix.sync.aligned.m8n8.x4.shared.b16 {%0,%1,%2,%3}, [%4];"
                             : "=r"(af[mi][0]), "=r"(af[mi][1]), "=r"(af[mi][2]), "=r"(af[mi][3])
                             : "r"(a) : "memory");
            }
            uint32_t bfr[2][4];
#pragma unroll
            for (int nb = 0; nb < 2; nb++) {
                // mats: (n0-7,k0-3),(n0-7,k4-7),(n8-15,k0-3),(n8-15,k4-7)
                const int nrow = wn * 32 + nb * 16 + br;
                const uint32_t a = smem_u32(Bs_ + nrow * ROWB + (kk * 8 + bc4) * 4);
                asm volatile("ldmatrix.sync.aligned.m8n8.x4.shared.b16 {%0,%1,%2,%3}, [%4];"
                             : "=r"(bfr[nb][0]), "=r"(bfr[nb][1]), "=r"(bfr[nb][2]), "=r"(bfr[nb][3])
                             : "r"(a) : "memory");
            }
#pragma unroll
            for (int mi = 0; mi < 4; mi++)
#pragma unroll
                for (int ni = 0; ni < 4; ni++) {
                    const uint32_t b0 = bfr[ni >> 1][(ni & 1) * 2];
                    const uint32_t b1 = bfr[ni >> 1][(ni & 1) * 2 + 1];
                    MMA_TF32(acc[mi][ni], af[mi][0], af[mi][1], af[mi][2], af[mi][3], b0, b1);
                }
        }
    }

    // epilogue (unchanged layout): 4 column slabs of 32, smem-staged
    float* Y = BATCHED ? ((z == 0) ? g_Q : (z == 1) ? g_K : g_V) : Yp;
    float* stg_ = (float*)smem;
    const int gid = lane >> 2, tid2 = (lane & 3) * 2;
#pragma unroll 1
    for (int cb = 0; cb < 4; cb++) {
        __syncthreads();
        if (wn == cb) {
#pragma unroll
            for (int mi = 0; mi < 4; mi++)
#pragma unroll
                for (int ni = 0; ni < 4; ni++) {
                    const int r = wm * 64 + mi * 16 + gid;
                    const int c = ni * 8 + tid2;
                    stg_[r * 36 + c]            = acc[mi][ni][0];
                    stg_[r * 36 + c + 1]        = acc[mi][ni][1];
                    stg_[(r + 8) * 36 + c]      = acc[mi][ni][2];
                    stg_[(r + 8) * 36 + c + 1]  = acc[mi][ni][3];
                }
        }
        __syncthreads();
        for (int e = t; e < 1024; e += 256) {
            const int r = e >> 3, c4 = (e & 7) * 4;
            float4 val = *(const float4*)&stg_[r * 36 + c4];
            const int n = n0 + cb * 32 + c4;
            const int m = m0 + r;
            if (!BATCHED) {
                *(float4*)(Y + (size_t)m * EMB + n) = val;
            } else {
                const int b = m >> 11, tt = m & 2047;
                const int h = n >> 6, d = n & 63;
                *(float4*)(Y + ((size_t)(b * NH + h) * T_SEQ + tt) * DH + d) = val;
            }
        }
    }
}

// ---------------------------------------------------------------------------
// tf32 tensor-core flash attention (causal), explicit fragment addressing.
// Epilogue writes tf32 words directly into g_A2[z=0] for the O-GEMM.
// ---------------------------------------------------------------------------
#define KST 68
#define VST 72
#define PST 68
#define SMEM_ATTN ((64 * KST + 64 * VST + 8 * 16 * PST) * 4)

__global__ void __launch_bounds__(256, 2) attn_tc_kernel()
{
    extern __shared__ float sm[];
    float* Ks = sm;
    float* Vs = sm + 64 * KST;
    float* Pw_base = sm + 64 * KST + 64 * VST;

    const int bh = blockIdx.y;
    const int qt = (int)gridDim.x - 1 - (int)blockIdx.x;
    const int q0 = qt * 128;
    const int t = threadIdx.x;
    const int w = t >> 5, lane = t & 31;
    const int g = lane >> 2, tig = lane & 3;

    const float* Qg = g_Q + (size_t)bh * T_SEQ * DH;
    const float* Kg = g_K + (size_t)bh * T_SEQ * DH;
    const float* Vg = g_V + (size_t)bh * T_SEQ * DH;

#pragma unroll
    for (int qq = 0; qq < 8; qq++) {
        const int idx = t + qq * 256;
        const int row = idx >> 4, c4 = (idx & 15) << 2;
        float4 f = *(const float4*)(Qg + (size_t)(q0 + row) * DH + c4);
        uint4 u;
        u.x = f2tf32(f.x * 0.125f); u.y = f2tf32(f.y * 0.125f);
        u.z = f2tf32(f.z * 0.125f); u.w = f2tf32(f.w * 0.125f);
        *(uint4*)(sm + row * KST + c4) = u;
    }
    __syncthreads();

    uint32_t qf[8][4];
    {
        const float* Qw = sm + (w * 16) * KST;
#pragma unroll
        for (int kc = 0; kc < 8; kc++) {
            qf[kc][0] = *(const uint32_t*)&Qw[g * KST + kc * 8 + tig];
            qf[kc][1] = *(const uint32_t*)&Qw[(g + 8) * KST + kc * 8 + tig];
            qf[kc][2] = *(const uint32_t*)&Qw[g * KST + kc * 8 + tig + 4];
            qf[kc][3] = *(const uint32_t*)&Qw[(g + 8) * KST + kc * 8 + tig + 4];
        }
    }
    __syncthreads();

    float o[8][4];
#pragma unroll
    for (int nt = 0; nt < 8; nt++)
#pragma unroll
        for (int j = 0; j < 4; j++) o[nt][j] = 0.f;
    float m0 = -1e30f, m1 = -1e30f, l0 = 0.f, l1 = 0.f;

    float* Pw = Pw_base + w * 16 * PST;

    const int ktmax = 2 * qt + 1;
    for (int kt = 0; kt <= ktmax; kt++) {
        const int k0 = kt * 64;
#pragma unroll
        for (int qq = 0; qq < 4; qq++) {
            const int idx = t + qq * 256;
            const int row = idx >> 4, c4 = (idx & 15) << 2;
            float4 fk = *(const float4*)(Kg + (size_t)(k0 + row) * DH + c4);
            float4 fv = *(const float4*)(Vg + (size_t)(k0 + row) * DH + c4);
            uint4 uk, uv;
            uk.x = f2tf32(fk.x); uk.y = f2tf32(fk.y); uk.z = f2tf32(fk.z); uk.w = f2tf32(fk.w);
            uv.x = f2tf32(fv.x); uv.y = f2tf32(fv.y); uv.z = f2tf32(fv.z); uv.w = f2tf32(fv.w);
            *(uint4*)(Ks + row * KST + c4) = uk;
            *(uint4*)(Vs + row * VST + c4) = uv;
        }
        __syncthreads();

        float s[8][4];
#pragma unroll
        for (int nt = 0; nt < 8; nt++) {
            s[nt][0] = 0.f; s[nt][1] = 0.f; s[nt][2] = 0.f; s[nt][3] = 0.f;
            const float* Kr = Ks + (nt * 8 + g) * KST + tig;
#pragma unroll
            for (int kc = 0; kc < 8; kc++) {
                const uint32_t b0 = *(const uint32_t*)&Kr[kc * 8];
                const uint32_t b1 = *(const uint32_t*)&Kr[kc * 8 + 4];
                MMA_TF32(s[nt], qf[kc][0], qf[kc][1], qf[kc][2], qf[kc][3], b0, b1);
            }
        }

        if (kt >= 2 * qt) {
            const int r0 = q0 + w * 16 + g, r1 = r0 + 8;
#pragma unroll
            for (int nt = 0; nt < 8; nt++) {
                const int c0 = k0 + nt * 8 + 2 * tig;
                if (c0     > r0) s[nt][0] = -1e30f;
                if (c0 + 1 > r0) s[nt][1] = -1e30f;
                if (c0     > r1) s[nt][2] = -1e30f;
                if (c0 + 1 > r1) s[nt][3] = -1e30f;
            }
        }

        float rm0 = -1e30f, rm1 = -1e30f;
#pragma unroll
        for (int nt = 0; nt < 8; nt++) {
            rm0 = fmaxf(rm0, fmaxf(s[nt][0], s[nt][1]));
            rm1 = fmaxf(rm1, fmaxf(s[nt][2], s[nt][3]));
        }
        rm0 = fmaxf(rm0, __shfl_xor_sync(0xffffffffu, rm0, 1));
        rm0 = fmaxf(rm0, __shfl_xor_sync(0xffffffffu, rm0, 2));
        rm1 = fmaxf(rm1, __shfl_xor_sync(0xffffffffu, rm1, 1));
        rm1 = fmaxf(rm1, __shfl_xor_sync(0xffffffffu, rm1, 2));
        const float mn0 = fmaxf(m0, rm0), mn1 = fmaxf(m1, rm1);
        const float a0 = __expf(m0 - mn0), a1 = __expf(m1 - mn1);
        float rs0 = 0.f, rs1 = 0.f;
#pragma unroll
        for (int nt = 0; nt < 8; nt++) {
            s[nt][0] = __expf(s[nt][0] - mn0); rs0 += s[nt][0];
            s[nt][1] = __expf(s[nt][1] - mn0); rs0 += s[nt][1];
            s[nt][2] = __expf(s[nt][2] - mn1); rs1 += s[nt][2];
            s[nt][3] = __expf(s[nt][3] - mn1); rs1 += s[nt][3];
        }
        rs0 += __shfl_xor_sync(0xffffffffu, rs0, 1);
        rs0 += __shfl_xor_sync(0xffffffffu, rs0, 2);
        rs1 += __shfl_xor_sync(0xffffffffu, rs1, 1);
        rs1 += __shfl_xor_sync(0xffffffffu, rs1, 2);
        l0 = l0 * a0 + rs0; m0 = mn0;
        l1 = l1 * a1 + rs1; m1 = mn1;
#pragma unroll
        for (int nt = 0; nt < 8; nt++) {
            o[nt][0] *= a0; o[nt][1] *= a0;
            o[nt][2] *= a1; o[nt][3] *= a1;
        }

#pragma unroll
        for (int nt = 0; nt < 8; nt++) {
            *(float2*)&Pw[g * PST + nt * 8 + 2 * tig]       = make_float2(s[nt][0], s[nt][1]);
            *(float2*)&Pw[(g + 8) * PST + nt * 8 + 2 * tig] = make_float2(s[nt][2], s[nt][3]);
        }
        __syncwarp();

#pragma unroll
        for (int kc = 0; kc < 8; kc++) {
            const uint32_t pa0 = f2tf32(Pw[g * PST + kc * 8 + tig]);
            const uint32_t pa1 = f2tf32(Pw[(g + 8) * PST + kc * 8 + tig]);
            const uint32_t pa2 = f2tf32(Pw[g * PST + kc * 8 + tig + 4]);
            const uint32_t pa3 = f2tf32(Pw[(g + 8) * PST + kc * 8 + tig + 4]);
            const float* Vr0 = Vs + (kc * 8 + tig) * VST + g;
            const float* Vr1 = Vs + (kc * 8 + tig + 4) * VST + g;
#pragma unroll
            for (int nt = 0; nt < 8; nt++) {
                const uint32_t b0 = *(const uint32_t*)&Vr0[nt * 8];
                const uint32_t b1 = *(const uint32_t*)&Vr1[nt * 8];
                MMA_TF32(o[nt], pa0, pa1, pa2, pa3, b0, b1);
            }
        }
        __syncthreads();
    }

    // epilogue: normalize + tf32 words into g_A2 (z=0) for the O-GEMM
    const int b = bh >> 4, h = bh & 15;
    const int r0 = q0 + w * 16 + g;
    const float inv0 = 1.0f / l0, inv1 = 1.0f / l1;
    uint32_t* row0 = g_A2 + (size_t)(b * T_SEQ + r0) * EMB;
    uint32_t* row1 = g_A2 + (size_t)(b * T_SEQ + r0 + 8) * EMB;
#pragma unroll
    for (int nt = 0; nt < 8; nt++) {
        const int col = h * DH + nt * 8 + 2 * tig;
        uint2 u0, u1;
        u0.x = f2tf32(o[nt][0] * inv0); u0.y = f2tf32(o[nt][1] * inv0);
        u1.x = f2tf32(o[nt][2] * inv1); u1.y = f2tf32(o[nt][3] * inv1);
        *(uint2*)&row0[col] = u0;
        *(uint2*)&row1[col] = u1;
    }
}

extern "C" void kernel_launch(void* const* d_in, const int* in_sizes, int n_in,
                              void* d_out, int out_size)
{
    (void)in_sizes; (void)n_in; (void)out_size;
    const float* q  = (const float*)d_in[0];
    const float* k  = (const float*)d_in[1];
    const float* v  = (const float*)d_in[2];
    const float* Wq = (const float*)d_in[3];
    const float* Wk = (const float*)d_in[4];
    const float* Wv = (const float*)d_in[5];
    const float* Wo = (const float*)d_in[6];
    float* out = (float*)d_out;

    static bool attr_set = false;
    if (!attr_set) {
        cudaFuncSetAttribute(attn_tc_kernel, cudaFuncAttributeMaxDynamicSharedMemorySize, SMEM_ATTN);
        cudaFuncSetAttribute(gemm_kernel<0>, cudaFuncAttributeMaxDynamicSharedMemorySize, SMEM_GEMM);
        cudaFuncSetAttribute(gemm_kernel<1>, cudaFuncAttributeMaxDynamicSharedMemorySize, SMEM_GEMM);
        attr_set = true;
    }

    conv_act<<<12288, 256>>>(q, k, v);
    conv_wgt<<<1024, 256>>>(Wq, 0);
    conv_wgt<<<1024, 256>>>(Wk, 1);
    conv_wgt<<<1024, 256>>>(Wv, 2);
    gemm_kernel<1><<<dim3(EMB / 128, NTOK / 128, 3), 256, SMEM_GEMM>>>(nullptr);

    attn_tc_kernel<<<dim3(T_SEQ / 128, BATCH * NH), 256, SMEM_ATTN>>>();

    conv_wgt<<<1024, 256>>>(Wo, 0);
    gemm_kernel<0><<<dim3(EMB / 128, NTOK / 128), 256, SMEM_GEMM>>>(out);
}